// round 13
// baseline (speedup 1.0000x reference)
#include <cuda_runtime.h>
#include <cuda_fp16.h>
#include <cstdint>

// GRU encoder B=512 T=128 E=H=512 L=2 — R13: R12 (fp16 1-pass HMMA + PDL)
// with the CTA's full 128KB weight slice made smem-RESIDENT, loaded before
// griddepcontrol.wait (overlaps predecessor). Mainloop waits only on 16KB
// A-stages (4-buffer, prefetch distance 3, one sync/iter).

namespace {

constexpr int B_ = 512, T_ = 128, H_ = 512, L_ = 2;
constexpr int NG = 1536;
constexpr size_t BH  = (size_t)B_ * H_;
constexpr size_t BNG = (size_t)B_ * NG;
constexpr size_t WSZ = (size_t)NG * 512;
constexpr int MT = 128, NT = 128, KC = 64;
constexpr int NITER = 512 / KC;            // 8
constexpr int CH = 16384;                  // 128 rows x 64 fp16 (SW128) = 16KB
constexpr int A_BASE = 8 * CH;             // B resident: 8 chunks = 128KB
constexpr int A_BUFS = 4;                  // 4 x 16KB A stages
constexpr int SMEM_ALLOC = A_BASE + A_BUFS * CH;   // 196608

__device__ __align__(256) float g_scr[3 * BNG];     // gh0 | gi1 | gh1
__device__ __align__(256) float g_P[128 * NG];      // emb @ Wi0^T (exact fp32)
__device__ __align__(256) __half g_W[3 * WSZ];      // fp16 W: Wh0 | Wi1 | Wh1
__device__ __align__(256) __half g_Ah[2 * BH];      // per-layer hidden, fp16

__device__ __forceinline__ uint32_t s2u(const void* p) {
    uint32_t a;
    asm("{ .reg .u64 t; cvta.to.shared.u64 t, %1; cvt.u32.u64 %0, t; }" : "=r"(a) : "l"(p));
    return a;
}
__device__ __forceinline__ uint32_t sw128(uint32_t b) { return b ^ ((b >> 3) & 0x70); }
__device__ __forceinline__ void cp16(uint32_t dst, const void* src) {
    asm volatile("cp.async.cg.shared.global [%0], [%1], 16;" :: "r"(dst), "l"(src));
}
__device__ __forceinline__ void ldsm4(uint32_t* r, uint32_t addr) {
    asm volatile("ldmatrix.sync.aligned.m8n8.x4.shared.b16 {%0,%1,%2,%3}, [%4];"
                 : "=r"(r[0]), "=r"(r[1]), "=r"(r[2]), "=r"(r[3]) : "r"(addr));
}
__device__ __forceinline__ void mma16816(float* c, const uint32_t* a, const uint32_t* b) {
    asm volatile(
        "mma.sync.aligned.m16n8k16.row.col.f32.f16.f16.f32 "
        "{%0,%1,%2,%3}, {%4,%5,%6,%7}, {%8,%9}, {%0,%1,%2,%3};"
        : "+f"(c[0]), "+f"(c[1]), "+f"(c[2]), "+f"(c[3])
        : "r"(a[0]), "r"(a[1]), "r"(a[2]), "r"(a[3]), "r"(b[0]), "r"(b[1]));
}
__device__ __forceinline__ void pdl_wait() {
    asm volatile("griddepcontrol.wait;" ::: "memory");
}
__device__ __forceinline__ void pdl_trigger() {
    asm volatile("griddepcontrol.launch_dependents;" ::: "memory");
}

// ============================ GEMM ============================
// job0: gh0 = h0(t-1) @ Wh0^T | job1: gi1 = h0(t-1) @ Wi1^T | job2: gh1 = h1(t-2) @ Wh1^T
__global__ void __launch_bounds__(256, 1) gemm_step(int t) {
    const int job = blockIdx.z;
    if (job == 0) { if (t >= T_) return; } else { if (t < 1) return; }

    const int a_sel = (job == 2) ? 1 : 0;
    const __half* __restrict__ Asrc = g_Ah + (size_t)a_sel * BH;
    const __half* __restrict__ Bsrc = g_W + (size_t)job * WSZ;
    float* __restrict__ dst = g_scr + (size_t)job * BNG;

    const int m0 = blockIdx.y * MT, n0 = blockIdx.x * NT;
    const int tid = threadIdx.x, wid = tid >> 5, lane = tid & 31;
    const int warp_m = wid & 3, warp_n = wid >> 2;    // 4M x 2N, warp tile 32x64

    extern __shared__ char smraw[];
    const uint32_t smb = s2u(smraw);

    // --- pre-sync: load the ENTIRE 128KB weight slice (independent of pred) ---
    #pragma unroll
    for (int c8 = 0; c8 < 8; c8++) {
        #pragma unroll
        for (int i = 0; i < 4; i++) {
            int c = tid + i * 256;
            int row = c >> 3, col = c & 7;
            cp16(smb + c8 * CH + sw128((uint32_t)(row * 128 + col * 16)),
                 Bsrc + (size_t)(n0 + row) * 512 + c8 * KC + col * 8);
        }
    }
    asm volatile("cp.async.commit_group;");            // g0 = all of B

    pdl_wait();                                        // predecessor triggered

    auto load_A = [&](int stage) {                     // 16KB, 4 cp16/thread
        const uint32_t st = smb + A_BASE + (stage & 3) * CH;
        #pragma unroll
        for (int i = 0; i < 4; i++) {
            int c = tid + i * 256;
            int row = c >> 3, col = c & 7;
            cp16(st + sw128((uint32_t)(row * 128 + col * 16)),
                 Asrc + (size_t)(m0 + row) * 512 + stage * KC + col * 8);
        }
        asm volatile("cp.async.commit_group;");
    };
    load_A(0);   // g1
    load_A(1);   // g2
    load_A(2);   // g3

    const int aRow  = warp_m * 32 + (lane & 15);
    const int aKsel = ((lane >> 4) & 1) * 16;
    const int bRow  = warp_n * 64 + ((lane >> 4) & 1) * 8 + (lane & 7);
    const int bKsel = ((lane >> 3) & 1) * 16;

    float acc[2][8][4];
    #pragma unroll
    for (int mi = 0; mi < 2; mi++)
        #pragma unroll
        for (int ni = 0; ni < 8; ni++)
            #pragma unroll
            for (int q = 0; q < 4; q++) acc[mi][ni][q] = 0.0f;

    for (int j = 0; j < NITER; j++) {
        // groups: g0=B, g_{s+1}=A stage s. Need g0..g_{j+1} done here.
        if (j < 6)      asm volatile("cp.async.wait_group 2;");
        else if (j == 6) asm volatile("cp.async.wait_group 1;");
        else             asm volatile("cp.async.wait_group 0;");
        __syncthreads();
        if (j + 3 < NITER) load_A(j + 3);     // buffer (j+3)&3 != j&3
        if (j == NITER - 1) pdl_trigger();    // all gmem A reads issued

        const uint32_t stA = smb + A_BASE + (j & 3) * CH;
        const uint32_t stB = smb + j * CH;    // resident B chunk j
        #pragma unroll
        for (int ks = 0; ks < KC / 16; ks++) {
            uint32_t a[2][4], b[4][4];
            #pragma unroll
            for (int mi = 0; mi < 2; mi++) {
                uint32_t off = sw128((uint32_t)((aRow + mi * 16) * 128 + ks * 32 + aKsel));
                ldsm4(a[mi], stA + off);
            }
            #pragma unroll
            for (int g = 0; g < 4; g++) {
                uint32_t off = sw128((uint32_t)((bRow + g * 16) * 128 + ks * 32 + bKsel));
                ldsm4(b[g], stB + off);
            }
            #pragma unroll
            for (int mi = 0; mi < 2; mi++)
                #pragma unroll
                for (int ni = 0; ni < 8; ni++)
                    mma16816(acc[mi][ni], a[mi], &b[ni >> 1][(ni & 1) * 2]);
        }
    }

    #pragma unroll
    for (int mi = 0; mi < 2; mi++) {
        int row = m0 + warp_m * 32 + mi * 16 + (lane >> 2);
        #pragma unroll
        for (int ni = 0; ni < 8; ni++) {
            int col = n0 + warp_n * 64 + ni * 8 + (lane & 3) * 2;
            *(float2*)(dst + (size_t)row * NG + col) =
                make_float2(acc[mi][ni][0], acc[mi][ni][1]);
            *(float2*)(dst + (size_t)(row + 8) * NG + col) =
                make_float2(acc[mi][ni][2], acc[mi][ni][3]);
        }
    }
}

// ============================ gates ============================
__global__ void __launch_bounds__(256) gate_step(
        float* __restrict__ out, const int* __restrict__ input,
        const float* __restrict__ h0init,
        const float* __restrict__ b_ih, const float* __restrict__ b_hh,
        int t, int write_final) {
    const int layer = blockIdx.y;
    const int s = (layer == 0) ? t : t - 1;
    if (s < 0 || s >= T_) return;          // exit counts as PDL trigger

    // successor gemm's pre-wait phase touches only g_W -> release early
    pdl_trigger();
    pdl_wait();                             // this step's gemm output ready

    const int e4 = blockIdx.x * 256 + threadIdx.x;
    const int b = e4 >> 7;
    const int h = (e4 & 127) * 4;

    float4 gi_r, gi_z, gi_n;
    if (layer == 0) {
        const float* P = g_P + (size_t)input[b * T_ + s] * NG;
        gi_r = *(const float4*)(P + h);
        gi_z = *(const float4*)(P + 512 + h);
        gi_n = *(const float4*)(P + 1024 + h);
    } else {
        const float* G = g_scr + BNG + (size_t)b * NG;
        gi_r = *(const float4*)(G + h);
        gi_z = *(const float4*)(G + 512 + h);
        gi_n = *(const float4*)(G + 1024 + h);
    }
    const float* GH = g_scr + (layer == 0 ? (size_t)0 : 2 * BNG) + (size_t)b * NG;
    float4 gh_r = *(const float4*)(GH + h);
    float4 gh_z = *(const float4*)(GH + 512 + h);
    float4 gh_n = *(const float4*)(GH + 1024 + h);

    const float* hp_ptr = (s == 0) ? (h0init + (size_t)layer * BH)
                                   : (out + (size_t)((s - 1) * L_ + layer) * BH);
    float4 hp = *(const float4*)(hp_ptr + (size_t)b * H_ + h);

    const float* bi = b_ih + layer * NG;
    const float* bh = b_hh + layer * NG;
    float4 bir = *(const float4*)(bi + h), biz = *(const float4*)(bi + 512 + h),
           bin = *(const float4*)(bi + 1024 + h);
    float4 bhr = *(const float4*)(bh + h), bhz = *(const float4*)(bh + 512 + h),
           bhn = *(const float4*)(bh + 1024 + h);

    float hv[4];
    #pragma unroll
    for (int i = 0; i < 4; i++) {
        float r = 1.0f / (1.0f + expf(-((&gi_r.x)[i] + (&bir.x)[i] + (&gh_r.x)[i] + (&bhr.x)[i])));
        float z = 1.0f / (1.0f + expf(-((&gi_z.x)[i] + (&biz.x)[i] + (&gh_z.x)[i] + (&bhz.x)[i])));
        float n = tanhf((&gi_n.x)[i] + (&bin.x)[i] + r * ((&gh_n.x)[i] + (&bhn.x)[i]));
        hv[i] = (1.0f - z) * n + z * (&hp.x)[i];
    }

    const size_t eoff = (size_t)b * H_ + h;
    *(float4*)(out + (size_t)(s * L_ + layer) * BH + eoff) =
        make_float4(hv[0], hv[1], hv[2], hv[3]);

    __half* ah = g_Ah + (size_t)layer * BH + eoff;
    #pragma unroll
    for (int i = 0; i < 4; i++) ah[i] = __float2half_rn(hv[i]);

    if (write_final && s == T_ - 1)
        *(float4*)(out + (size_t)T_ * L_ * BH + (size_t)layer * BH + eoff) =
            make_float4(hv[0], hv[1], hv[2], hv[3]);
}

// ============================ prep ============================
// P[v][n] = sum_k emb[v][k] * Wi0[n][k], exact fp32. grid (12, 8): 16v x 128n tile.
__global__ void __launch_bounds__(256) prep_P(const float* __restrict__ emb,
                                              const float* __restrict__ w_ih) {
    const int n0 = blockIdx.x * 128;
    const int v0 = blockIdx.y * 16;
    const int tid = threadIdx.x;
    const int nq = tid & 31;       // owns n0 + nq*4 .. +3
    const int vq = tid >> 5;       // owns v0 + vq, v0 + vq + 8

    __shared__ float ws[32][132];   // [k][n], 132 keeps float4 alignment
    __shared__ float es[32][17];    // [k][v]

    float acc[2][4];
    #pragma unroll
    for (int i = 0; i < 2; i++)
        #pragma unroll
        for (int j = 0; j < 4; j++) acc[i][j] = 0.0f;

    for (int k0 = 0; k0 < 512; k0 += 32) {
        __syncthreads();
        {
            int k = tid & 31, v = tid >> 5;
            es[k][v]     = emb[(size_t)(v0 + v) * 512 + k0 + k];
            es[k][v + 8] = emb[(size_t)(v0 + v + 8) * 512 + k0 + k];
        }
        #pragma unroll
        for (int p = 0; p < 16; p++) {
            int idx = tid + p * 256, k = idx & 31, n = idx >> 5;
            ws[k][n] = w_ih[(size_t)(n0 + n) * 512 + k0 + k];
        }
        __syncthreads();
        #pragma unroll 8
        for (int kk = 0; kk < 32; kk++) {
            float a0 = es[kk][vq], a1 = es[kk][vq + 8];
            float4 w = *(const float4*)&ws[kk][nq * 4];
            #pragma unroll
            for (int j = 0; j < 4; j++) {
                acc[0][j] = fmaf(a0, (&w.x)[j], acc[0][j]);
                acc[1][j] = fmaf(a1, (&w.x)[j], acc[1][j]);
            }
        }
    }

    *(float4*)&g_P[(size_t)(v0 + vq) * NG + n0 + nq * 4] =
        make_float4(acc[0][0], acc[0][1], acc[0][2], acc[0][3]);
    *(float4*)&g_P[(size_t)(v0 + vq + 8) * NG + n0 + nq * 4] =
        make_float4(acc[1][0], acc[1][1], acc[1][2], acc[1][3]);
}

__global__ void __launch_bounds__(256) prep_W(const float* __restrict__ w_ih,
                                              const float* __restrict__ w_hh) {
    size_t e4 = ((size_t)blockIdx.x * 256 + threadIdx.x) * 4;
    size_t job = e4 / WSZ, off = e4 % WSZ;
    const float* src = (job == 0) ? (w_hh + off)
                     : (job == 1) ? (w_ih + WSZ + off) : (w_hh + WSZ + off);
    float4 v = *(const float4*)src;
    union { __half b[4]; uint2 u; } hh;
    hh.b[0] = __float2half_rn(v.x); hh.b[1] = __float2half_rn(v.y);
    hh.b[2] = __float2half_rn(v.z); hh.b[3] = __float2half_rn(v.w);
    *(uint2*)(g_W + e4) = hh.u;
}

__global__ void __launch_bounds__(256) prep_A(const float* __restrict__ h0) {
    size_t e4 = ((size_t)blockIdx.x * 256 + threadIdx.x) * 4;
    float4 v = *(const float4*)(h0 + e4);
    union { __half b[4]; uint2 u; } hh;
    hh.b[0] = __float2half_rn(v.x); hh.b[1] = __float2half_rn(v.y);
    hh.b[2] = __float2half_rn(v.z); hh.b[3] = __float2half_rn(v.w);
    *(uint2*)(g_Ah + e4) = hh.u;
}

} // namespace

extern "C" void kernel_launch(void* const* d_in, const int* in_sizes, int n_in,
                              void* d_out, int out_size) {
    const int*   input = (const int*)  d_in[0];
    const float* h0    = (const float*)d_in[1];
    const float* emb   = (const float*)d_in[2];
    const float* w_ih  = (const float*)d_in[3];
    const float* w_hh  = (const float*)d_in[4];
    const float* b_ih  = (const float*)d_in[5];
    const float* b_hh  = (const float*)d_in[6];
    float* out = (float*)d_out;

    const long long states_elems = (long long)T_ * L_ * B_ * H_;
    int write_final =
        ((long long)out_size >= states_elems + (long long)L_ * B_ * H_) ? 1 : 0;

    cudaFuncSetAttribute(gemm_step, cudaFuncAttributeMaxDynamicSharedMemorySize, SMEM_ALLOC);

    prep_W<<<(int)(3 * WSZ / 4 / 256), 256>>>(w_ih, w_hh);
    prep_A<<<(int)(2 * BH / 4 / 256), 256>>>(h0);
    prep_P<<<dim3(12, 8), 256>>>(emb, w_ih);

    cudaLaunchAttribute attrs[1];
    attrs[0].id = cudaLaunchAttributeProgrammaticStreamSerialization;
    attrs[0].val.programmaticStreamSerializationAllowed = 1;

    for (int t = 0; t <= T_; t++) {
        {
            cudaLaunchConfig_t cfg = {};
            cfg.gridDim = dim3(NG / NT, B_ / MT, 3);
            cfg.blockDim = dim3(256);
            cfg.dynamicSmemBytes = SMEM_ALLOC;
            cfg.stream = 0;
            cfg.attrs = attrs;
            cfg.numAttrs = 1;
            void* args[] = {&t};
            cudaLaunchKernelExC(&cfg, (const void*)gemm_step, args);
        }
        {
            cudaLaunchConfig_t cfg = {};
            cfg.gridDim = dim3(256, 2);
            cfg.blockDim = dim3(256);
            cfg.dynamicSmemBytes = 0;
            cfg.stream = 0;
            cfg.attrs = attrs;
            cfg.numAttrs = 1;
            void* args[] = {&out, &input, &h0, &b_ih, &b_hh, &t, &write_final};
            cudaLaunchKernelExC(&cfg, (const void*)gate_step, args);
        }
    }
}

// round 14
// speedup vs baseline: 1.1088x; 1.1088x over previous
#include <cuda_runtime.h>
#include <cuda_fp16.h>
#include <cstdint>

// GRU encoder B=512 T=128 E=H=512 L=2 — R14: R12 (fp16 1-pass HMMA + PDL,
// KC=128, 3x64KB stages) + manual fragment double-buffering in the k-step
// loop: LDSM for step k+1 issues before the MMAs of step k, breaking the
// per-step LDSM->HMMA latency chain that 2 warps/SMSP can't hide.

namespace {

constexpr int B_ = 512, T_ = 128, H_ = 512, L_ = 2;
constexpr int NG = 1536;
constexpr size_t BH  = (size_t)B_ * H_;
constexpr size_t BNG = (size_t)B_ * NG;
constexpr size_t WSZ = (size_t)NG * 512;
constexpr int MT = 128, NT = 128;
constexpr int CH = 16384;                  // one 128x64 fp16 chunk (SW128)
constexpr int A_OFF = 0, B_OFF = 2 * CH;   // stage: A(2 chunks) | B(2 chunks)
constexpr int STAGE = 4 * CH;              // 65536
constexpr int SMEM_ALLOC = 3 * STAGE;      // 196608

__device__ __align__(256) float g_scr[3 * BNG];     // gh0 | gi1 | gh1
__device__ __align__(256) float g_P[128 * NG];      // emb @ Wi0^T (exact fp32)
__device__ __align__(256) __half g_W[3 * WSZ];      // fp16 W: Wh0 | Wi1 | Wh1
__device__ __align__(256) __half g_Ah[2 * BH];      // per-layer hidden, fp16

__device__ __forceinline__ uint32_t s2u(const void* p) {
    uint32_t a;
    asm("{ .reg .u64 t; cvta.to.shared.u64 t, %1; cvt.u32.u64 %0, t; }" : "=r"(a) : "l"(p));
    return a;
}
__device__ __forceinline__ uint32_t sw128(uint32_t b) { return b ^ ((b >> 3) & 0x70); }
__device__ __forceinline__ void cp16(uint32_t dst, const void* src) {
    asm volatile("cp.async.cg.shared.global [%0], [%1], 16;" :: "r"(dst), "l"(src));
}
__device__ __forceinline__ void ldsm4(uint32_t* r, uint32_t addr) {
    asm volatile("ldmatrix.sync.aligned.m8n8.x4.shared.b16 {%0,%1,%2,%3}, [%4];"
                 : "=r"(r[0]), "=r"(r[1]), "=r"(r[2]), "=r"(r[3]) : "r"(addr));
}
__device__ __forceinline__ void mma16816(float* c, const uint32_t* a, const uint32_t* b) {
    asm volatile(
        "mma.sync.aligned.m16n8k16.row.col.f32.f16.f16.f32 "
        "{%0,%1,%2,%3}, {%4,%5,%6,%7}, {%8,%9}, {%0,%1,%2,%3};"
        : "+f"(c[0]), "+f"(c[1]), "+f"(c[2]), "+f"(c[3])
        : "r"(a[0]), "r"(a[1]), "r"(a[2]), "r"(a[3]), "r"(b[0]), "r"(b[1]));
}
__device__ __forceinline__ void pdl_wait() {
    asm volatile("griddepcontrol.wait;" ::: "memory");
}
__device__ __forceinline__ void pdl_trigger() {
    asm volatile("griddepcontrol.launch_dependents;" ::: "memory");
}

// ============================ GEMM ============================
// job0: gh0 = h0(t-1) @ Wh0^T | job1: gi1 = h0(t-1) @ Wi1^T | job2: gh1 = h1(t-2) @ Wh1^T
__global__ void __launch_bounds__(256, 1) gemm_step(int t) {
    const int job = blockIdx.z;
    if (job == 0) { if (t >= T_) return; } else { if (t < 1) return; }

    const int a_sel = (job == 2) ? 1 : 0;
    const __half* __restrict__ Asrc = g_Ah + (size_t)a_sel * BH;
    const __half* __restrict__ Bsrc = g_W + (size_t)job * WSZ;
    float* __restrict__ dst = g_scr + (size_t)job * BNG;

    const int m0 = blockIdx.y * MT, n0 = blockIdx.x * NT;
    const int tid = threadIdx.x, wid = tid >> 5, lane = tid & 31;
    const int warp_m = wid & 3, warp_n = wid >> 2;    // 4M x 2N, warp tile 32x64

    extern __shared__ char smraw[];
    const uint32_t smb = s2u(smraw);

    auto load_B = [&](int buf, int k0) {   // both 64-wide chunks of a 128-K stage
        const uint32_t st = smb + buf * STAGE + B_OFF;
        #pragma unroll
        for (int ch = 0; ch < 2; ch++)
            #pragma unroll
            for (int i = 0; i < 4; i++) {
                int c = tid + i * 256;
                int row = c >> 3, col = c & 7;
                cp16(st + ch * CH + sw128((uint32_t)(row * 128 + col * 16)),
                     Bsrc + (size_t)(n0 + row) * 512 + k0 + ch * 64 + col * 8);
            }
    };
    auto load_A = [&](int buf, int k0) {
        const uint32_t st = smb + buf * STAGE + A_OFF;
        #pragma unroll
        for (int ch = 0; ch < 2; ch++)
            #pragma unroll
            for (int i = 0; i < 4; i++) {
                int c = tid + i * 256;
                int row = c >> 3, col = c & 7;
                cp16(st + ch * CH + sw128((uint32_t)(row * 128 + col * 16)),
                     Asrc + (size_t)(m0 + row) * 512 + k0 + ch * 64 + col * 8);
            }
    };

    // --- pre-sync phase: weights only (independent of predecessor) ---
    load_B(0, 0); load_B(1, 128); load_B(2, 256);
    asm volatile("cp.async.commit_group;");            // g0
    pdl_wait();                                        // predecessor completed
    load_A(0, 0);   asm volatile("cp.async.commit_group;");  // g1
    load_A(1, 128); asm volatile("cp.async.commit_group;");  // g2
    load_A(2, 256); asm volatile("cp.async.commit_group;");  // g3

    const int aRow  = warp_m * 32 + (lane & 15);
    const int aKsel = ((lane >> 4) & 1) * 16;
    const int bRow  = warp_n * 64 + ((lane >> 4) & 1) * 8 + (lane & 7);
    const int bKsel = ((lane >> 3) & 1) * 16;

    float acc[2][8][4];
    #pragma unroll
    for (int mi = 0; mi < 2; mi++)
        #pragma unroll
        for (int ni = 0; ni < 8; ni++)
            #pragma unroll
            for (int q = 0; q < 4; q++) acc[mi][ni][q] = 0.0f;

    // fragment double buffers
    uint32_t af[2][2][4], bf[2][4][4];

    auto load_frags = [&](uint32_t stA, uint32_t stB, int k16, int set) {
        const int ch = k16 >> 2;          // 64-fp16 chunk within stage
        const int ks = k16 & 3;           // 16-fp16 step within chunk
        #pragma unroll
        for (int mi = 0; mi < 2; mi++) {
            uint32_t off = sw128((uint32_t)((aRow + mi * 16) * 128 + ks * 32 + aKsel));
            ldsm4(af[set][mi], stA + ch * CH + off);
        }
        #pragma unroll
        for (int g = 0; g < 4; g++) {
            uint32_t off = sw128((uint32_t)((bRow + g * 16) * 128 + ks * 32 + bKsel));
            ldsm4(bf[set][g], stB + ch * CH + off);
        }
    };
    auto mma_set = [&](int set) {
        #pragma unroll
        for (int mi = 0; mi < 2; mi++)
            #pragma unroll
            for (int ni = 0; ni < 8; ni++)
                mma16816(acc[mi][ni], af[set][mi], &bf[set][ni >> 1][(ni & 1) * 2]);
    };

    #pragma unroll
    for (int js = 0; js < 4; js++) {
        if (js == 0)      asm volatile("cp.async.wait_group 2;");
        else if (js == 3) asm volatile("cp.async.wait_group 0;");
        else              asm volatile("cp.async.wait_group 1;");
        __syncthreads();
        if (js == 1) {                      // buf0 consumed -> refill for js=3
            load_B(0, 384); load_A(0, 384);
            asm volatile("cp.async.commit_group;");    // g4
        }
        if (js == 3) pdl_trigger();         // schedule successor (wait = completion)

        const int buf = js % 3;
        const uint32_t stA = smb + buf * STAGE + A_OFF;
        const uint32_t stB = smb + buf * STAGE + B_OFF;

        load_frags(stA, stB, 0, 0);         // prime set 0
        #pragma unroll
        for (int k16 = 0; k16 < 8; k16++) {
            const int cur = k16 & 1;
            if (k16 < 7) load_frags(stA, stB, k16 + 1, cur ^ 1);  // prefetch next
            mma_set(cur);
        }
    }

    #pragma unroll
    for (int mi = 0; mi < 2; mi++) {
        int row = m0 + warp_m * 32 + mi * 16 + (lane >> 2);
        #pragma unroll
        for (int ni = 0; ni < 8; ni++) {
            int col = n0 + warp_n * 64 + ni * 8 + (lane & 3) * 2;
            *(float2*)(dst + (size_t)row * NG + col) =
                make_float2(acc[mi][ni][0], acc[mi][ni][1]);
            *(float2*)(dst + (size_t)(row + 8) * NG + col) =
                make_float2(acc[mi][ni][2], acc[mi][ni][3]);
        }
    }
}

// ============================ gates ============================
__global__ void __launch_bounds__(256) gate_step(
        float* __restrict__ out, const int* __restrict__ input,
        const float* __restrict__ h0init,
        const float* __restrict__ b_ih, const float* __restrict__ b_hh,
        int t, int write_final) {
    const int layer = blockIdx.y;
    const int s = (layer == 0) ? t : t - 1;
    if (s < 0 || s >= T_) return;          // exit counts as PDL trigger

    // successor gemm's pre-wait phase touches only g_W -> release scheduling now
    pdl_trigger();
    pdl_wait();                             // gemm grid fully complete

    const int e4 = blockIdx.x * 256 + threadIdx.x;
    const int b = e4 >> 7;
    const int h = (e4 & 127) * 4;

    float4 gi_r, gi_z, gi_n;
    if (layer == 0) {
        const float* P = g_P + (size_t)input[b * T_ + s] * NG;
        gi_r = *(const float4*)(P + h);
        gi_z = *(const float4*)(P + 512 + h);
        gi_n = *(const float4*)(P + 1024 + h);
    } else {
        const float* G = g_scr + BNG + (size_t)b * NG;
        gi_r = *(const float4*)(G + h);
        gi_z = *(const float4*)(G + 512 + h);
        gi_n = *(const float4*)(G + 1024 + h);
    }
    const float* GH = g_scr + (layer == 0 ? (size_t)0 : 2 * BNG) + (size_t)b * NG;
    float4 gh_r = *(const float4*)(GH + h);
    float4 gh_z = *(const float4*)(GH + 512 + h);
    float4 gh_n = *(const float4*)(GH + 1024 + h);

    const float* hp_ptr = (s == 0) ? (h0init + (size_t)layer * BH)
                                   : (out + (size_t)((s - 1) * L_ + layer) * BH);
    float4 hp = *(const float4*)(hp_ptr + (size_t)b * H_ + h);

    const float* bi = b_ih + layer * NG;
    const float* bh = b_hh + layer * NG;
    float4 bir = *(const float4*)(bi + h), biz = *(const float4*)(bi + 512 + h),
           bin = *(const float4*)(bi + 1024 + h);
    float4 bhr = *(const float4*)(bh + h), bhz = *(const float4*)(bh + 512 + h),
           bhn = *(const float4*)(bh + 1024 + h);

    float hv[4];
    #pragma unroll
    for (int i = 0; i < 4; i++) {
        float r = 1.0f / (1.0f + expf(-((&gi_r.x)[i] + (&bir.x)[i] + (&gh_r.x)[i] + (&bhr.x)[i])));
        float z = 1.0f / (1.0f + expf(-((&gi_z.x)[i] + (&biz.x)[i] + (&gh_z.x)[i] + (&bhz.x)[i])));
        float n = tanhf((&gi_n.x)[i] + (&bin.x)[i] + r * ((&gh_n.x)[i] + (&bhn.x)[i]));
        hv[i] = (1.0f - z) * n + z * (&hp.x)[i];
    }

    const size_t eoff = (size_t)b * H_ + h;
    *(float4*)(out + (size_t)(s * L_ + layer) * BH + eoff) =
        make_float4(hv[0], hv[1], hv[2], hv[3]);

    __half* ah = g_Ah + (size_t)layer * BH + eoff;
    #pragma unroll
    for (int i = 0; i < 4; i++) ah[i] = __float2half_rn(hv[i]);

    if (write_final && s == T_ - 1)
        *(float4*)(out + (size_t)T_ * L_ * BH + (size_t)layer * BH + eoff) =
            make_float4(hv[0], hv[1], hv[2], hv[3]);
}

// ============================ prep ============================
// P[v][n] = sum_k emb[v][k] * Wi0[n][k], exact fp32. grid (12, 8): 16v x 128n tile.
__global__ void __launch_bounds__(256) prep_P(const float* __restrict__ emb,
                                              const float* __restrict__ w_ih) {
    const int n0 = blockIdx.x * 128;
    const int v0 = blockIdx.y * 16;
    const int tid = threadIdx.x;
    const int nq = tid & 31;
    const int vq = tid >> 5;

    __shared__ float ws[32][132];
    __shared__ float es[32][17];

    float acc[2][4];
    #pragma unroll
    for (int i = 0; i < 2; i++)
        #pragma unroll
        for (int j = 0; j < 4; j++) acc[i][j] = 0.0f;

    for (int k0 = 0; k0 < 512; k0 += 32) {
        __syncthreads();
        {
            int k = tid & 31, v = tid >> 5;
            es[k][v]     = emb[(size_t)(v0 + v) * 512 + k0 + k];
            es[k][v + 8] = emb[(size_t)(v0 + v + 8) * 512 + k0 + k];
        }
        #pragma unroll
        for (int p = 0; p < 16; p++) {
            int idx = tid + p * 256, k = idx & 31, n = idx >> 5;
            ws[k][n] = w_ih[(size_t)(n0 + n) * 512 + k0 + k];
        }
        __syncthreads();
        #pragma unroll 8
        for (int kk = 0; kk < 32; kk++) {
            float a0 = es[kk][vq], a1 = es[kk][vq + 8];
            float4 w = *(const float4*)&ws[kk][nq * 4];
            #pragma unroll
            for (int j = 0; j < 4; j++) {
                acc[0][j] = fmaf(a0, (&w.x)[j], acc[0][j]);
                acc[1][j] = fmaf(a1, (&w.x)[j], acc[1][j]);
            }
        }
    }

    *(float4*)&g_P[(size_t)(v0 + vq) * NG + n0 + nq * 4] =
        make_float4(acc[0][0], acc[0][1], acc[0][2], acc[0][3]);
    *(float4*)&g_P[(size_t)(v0 + vq + 8) * NG + n0 + nq * 4] =
        make_float4(acc[1][0], acc[1][1], acc[1][2], acc[1][3]);
}

__global__ void __launch_bounds__(256) prep_W(const float* __restrict__ w_ih,
                                              const float* __restrict__ w_hh) {
    size_t e4 = ((size_t)blockIdx.x * 256 + threadIdx.x) * 4;
    size_t job = e4 / WSZ, off = e4 % WSZ;
    const float* src = (job == 0) ? (w_hh + off)
                     : (job == 1) ? (w_ih + WSZ + off) : (w_hh + WSZ + off);
    float4 v = *(const float4*)src;
    union { __half b[4]; uint2 u; } hh;
    hh.b[0] = __float2half_rn(v.x); hh.b[1] = __float2half_rn(v.y);
    hh.b[2] = __float2half_rn(v.z); hh.b[3] = __float2half_rn(v.w);
    *(uint2*)(g_W + e4) = hh.u;
}

__global__ void __launch_bounds__(256) prep_A(const float* __restrict__ h0) {
    size_t e4 = ((size_t)blockIdx.x * 256 + threadIdx.x) * 4;
    float4 v = *(const float4*)(h0 + e4);
    union { __half b[4]; uint2 u; } hh;
    hh.b[0] = __float2half_rn(v.x); hh.b[1] = __float2half_rn(v.y);
    hh.b[2] = __float2half_rn(v.z); hh.b[3] = __float2half_rn(v.w);
    *(uint2*)(g_Ah + e4) = hh.u;
}

} // namespace

extern "C" void kernel_launch(void* const* d_in, const int* in_sizes, int n_in,
                              void* d_out, int out_size) {
    const int*   input = (const int*)  d_in[0];
    const float* h0    = (const float*)d_in[1];
    const float* emb   = (const float*)d_in[2];
    const float* w_ih  = (const float*)d_in[3];
    const float* w_hh  = (const float*)d_in[4];
    const float* b_ih  = (const float*)d_in[5];
    const float* b_hh  = (const float*)d_in[6];
    float* out = (float*)d_out;

    const long long states_elems = (long long)T_ * L_ * B_ * H_;
    int write_final =
        ((long long)out_size >= states_elems + (long long)L_ * B_ * H_) ? 1 : 0;

    cudaFuncSetAttribute(gemm_step, cudaFuncAttributeMaxDynamicSharedMemorySize, SMEM_ALLOC);

    prep_W<<<(int)(3 * WSZ / 4 / 256), 256>>>(w_ih, w_hh);
    prep_A<<<(int)(2 * BH / 4 / 256), 256>>>(h0);
    prep_P<<<dim3(12, 8), 256>>>(emb, w_ih);

    cudaLaunchAttribute attrs[1];
    attrs[0].id = cudaLaunchAttributeProgrammaticStreamSerialization;
    attrs[0].val.programmaticStreamSerializationAllowed = 1;

    for (int t = 0; t <= T_; t++) {
        {
            cudaLaunchConfig_t cfg = {};
            cfg.gridDim = dim3(NG / NT, B_ / MT, 3);
            cfg.blockDim = dim3(256);
            cfg.dynamicSmemBytes = SMEM_ALLOC;
            cfg.stream = 0;
            cfg.attrs = attrs;
            cfg.numAttrs = 1;
            void* args[] = {&t};
            cudaLaunchKernelExC(&cfg, (const void*)gemm_step, args);
        }
        {
            cudaLaunchConfig_t cfg = {};
            cfg.gridDim = dim3(256, 2);
            cfg.blockDim = dim3(256);
            cfg.dynamicSmemBytes = 0;
            cfg.stream = 0;
            cfg.attrs = attrs;
            cfg.numAttrs = 1;
            void* args[] = {&out, &input, &h0, &b_ih, &b_hh, &t, &write_final};
            cudaLaunchKernelExC(&cfg, (const void*)gate_step, args);
        }
    }
}